// round 5
// baseline (speedup 1.0000x reference)
#include <cuda_runtime.h>
#include <cstdint>

// ============================================================================
// Binary CNN (XNOR-net style), fully fused:
//   conv1 (exact fp32, XLA/Eigen-order FMA chain) + b1 + relu + bn1 -> sign
//   conv2..conv6: bitpacked XNOR-popcount conv -> relu -> [pool] -> bn -> sign
//   conv6 emits float (bn6 applied), then fp32 dense(512->10) + softmax.
//
// Numerics: reference is full fp32 (TF32 emulation in R2 made error 10x
// worse, so the reference conv/dense are NOT TF32). Binary conv dots are
// exact small integers in fp32 in ANY summation order -> layers 2..6 are
// bit-exact by construction. The only rounding-order-sensitive op feeding a
// sign() threshold is conv1: emulate XLA exactly -- sequential FMA over
// k=(ky,kx,ci) row-major from acc=0, then separately rounded +b1, relu,
// *scale, +bias (no FMA contraction in the elementwise chain).
// (Resubmission of R3: infra failed twice before the kernel ever ran.)
// ============================================================================

#define DEVFN __device__ __forceinline__

// ---------------- scratch (device globals; no allocation) -------------------
__device__ unsigned int g_xb1[128 * 32 * 32 * 4];   // after conv1 block (sign bits)
__device__ unsigned int g_xb2[128 * 16 * 16 * 4];   // after conv2 block
__device__ unsigned int g_xb3[128 * 16 * 16 * 8];   // after conv3 block
__device__ unsigned int g_xb4[128 * 8 * 8 * 8];     // after conv4 block
__device__ unsigned int g_xb5[128 * 8 * 8 * 16];    // after conv5 block
__device__ float        g_h6[128 * 4 * 4 * 512];    // after conv6 block (float)

__device__ unsigned int g_wb2[9 * 128 * 4];   // packed weights [tap][co][ciw]
__device__ unsigned int g_wb3[9 * 256 * 4];
__device__ unsigned int g_wb4[9 * 256 * 8];
__device__ unsigned int g_wb5[9 * 512 * 8];
__device__ unsigned int g_wb6[9 * 512 * 16];

// ---------------- per-layer config ------------------------------------------
template <int L> struct Cfg;
template <> struct Cfg<2> { static constexpr int H = 32, W = 32, CI = 128, CO = 128; static constexpr bool POOL = true,  OUTF = false; };
template <> struct Cfg<3> { static constexpr int H = 16, W = 16, CI = 128, CO = 256; static constexpr bool POOL = false, OUTF = false; };
template <> struct Cfg<4> { static constexpr int H = 16, W = 16, CI = 256, CO = 256; static constexpr bool POOL = true,  OUTF = false; };
template <> struct Cfg<5> { static constexpr int H = 8,  W = 8,  CI = 256, CO = 512; static constexpr bool POOL = false, OUTF = false; };
template <> struct Cfg<6> { static constexpr int H = 8,  W = 8,  CI = 512, CO = 512; static constexpr bool POOL = true,  OUTF = true;  };

template <int L> DEVFN const unsigned int* bc_in();
template <> DEVFN const unsigned int* bc_in<2>() { return g_xb1; }
template <> DEVFN const unsigned int* bc_in<3>() { return g_xb2; }
template <> DEVFN const unsigned int* bc_in<4>() { return g_xb3; }
template <> DEVFN const unsigned int* bc_in<5>() { return g_xb4; }
template <> DEVFN const unsigned int* bc_in<6>() { return g_xb5; }

template <int L> DEVFN unsigned int* bc_out();
template <> DEVFN unsigned int* bc_out<2>() { return g_xb2; }
template <> DEVFN unsigned int* bc_out<3>() { return g_xb3; }
template <> DEVFN unsigned int* bc_out<4>() { return g_xb4; }
template <> DEVFN unsigned int* bc_out<5>() { return g_xb5; }
template <> DEVFN unsigned int* bc_out<6>() { return g_xb5; }  // unused (OUTF)

template <int L> DEVFN unsigned int* wb_ptr();
template <> DEVFN unsigned int* wb_ptr<2>() { return g_wb2; }
template <> DEVFN unsigned int* wb_ptr<3>() { return g_wb3; }
template <> DEVFN unsigned int* wb_ptr<4>() { return g_wb4; }
template <> DEVFN unsigned int* wb_ptr<5>() { return g_wb5; }
template <> DEVFN unsigned int* wb_ptr<6>() { return g_wb6; }

// ---------------- weight sign-packing ---------------------------------------
// Input HWIO: w[ky][kx][ci][co].  Output: wb[(tap*CO + co)*CIW + wi],
// bit b of word wi  <->  ci = wi*32 + b, bit=1 <=> w > 0  (i.e. sign +1).
// (sign(0) = 0 in the reference; treating it as -1 for BOTH x and w is an
// event of measure zero for x and consistent thresholding handles w=0 never
// occurring in random normals.)
template <int L>
__global__ void pack_kernel(const float* __restrict__ w) {
    constexpr int CI = Cfg<L>::CI, CO = Cfg<L>::CO, CIW = CI / 32;
    int idx = blockIdx.x * blockDim.x + threadIdx.x;
    if (idx >= 9 * CO * CIW) return;
    int wi  = idx % CIW;
    int co  = (idx / CIW) % CO;
    int tap = idx / (CIW * CO);
    unsigned int word = 0;
    #pragma unroll 8
    for (int b = 0; b < 32; b++) {
        float v = w[(tap * CI + wi * 32 + b) * CO + co];
        word |= (v > 0.f ? (1u << b) : 0u);
    }
    wb_ptr<L>()[idx] = word;
}

// ---------------- conv1: fp32 conv + b1 + relu + bn1 -> sign bits -----------
// grid (32 rows, 128 images), block 128 (= output channels)
// Arithmetic mirrors XLA: conv = sequential FMA over (ky,kx,ci) from 0;
// then separately rounded +b1, relu, *scale, +bias.
__global__ void __launch_bounds__(128) conv1_kernel(
    const float* __restrict__ x,  const float* __restrict__ w1,
    const float* __restrict__ b1, const float* __restrict__ bn_s,
    const float* __restrict__ bn_b) {
    __shared__ float ws[27 * 128];
    __shared__ float xr[3][34][3];   // 3 rows, 34 cols (zero-padded), 3 ch
    int co = threadIdx.x;
    int y = blockIdx.x, n = blockIdx.y;

    for (int i = co; i < 27 * 128; i += 128) ws[i] = w1[i];
    for (int i = co; i < 3 * 34 * 3; i += 128) {
        int r = i / 102, rem = i % 102;
        int col = rem / 3, ci = rem % 3;
        int iy = y - 1 + r, ix = col - 1;
        float v = 0.f;
        if (iy >= 0 && iy < 32 && ix >= 0 && ix < 32)
            v = x[((n * 32 + iy) * 32 + ix) * 3 + ci];
        xr[r][col][ci] = v;
    }
    float sc = bn_s[co], bb = bn_b[co], bias1 = b1[co];
    __syncthreads();

    int lane = co & 31, wq = co >> 5;
    for (int xx = 0; xx < 32; xx++) {
        float acc = 0.f;
        #pragma unroll
        for (int ky = 0; ky < 3; ky++)
            #pragma unroll
            for (int kx = 0; kx < 3; kx++)
                #pragma unroll
                for (int ci = 0; ci < 3; ci++)
                    acc = __fmaf_rn(xr[ky][xx + kx][ci],
                                    ws[((ky * 3 + kx) * 3 + ci) * 128 + co], acc);
        float h = fmaxf(__fadd_rn(acc, bias1), 0.f);
        float f = __fadd_rn(__fmul_rn(h, sc), bb);   // XLA-style mul then add
        unsigned int bits = __ballot_sync(0xffffffffu, f > 0.f);
        if (lane == 0) g_xb1[((n * 32 + y) * 32 + xx) * 4 + wq] = bits;
    }
}

// ---------------- binary conv (fused relu/pool/bn/sign) ----------------------
// grid (N=128, CO/32), block 256. Warp lanes <-> 32 consecutive out-channels.
template <int L>
__global__ void __launch_bounds__(256) binconv_kernel(
    const float* __restrict__ scale, const float* __restrict__ bias) {
    constexpr int  H = Cfg<L>::H, W = Cfg<L>::W, CI = Cfg<L>::CI, CO = Cfg<L>::CO;
    constexpr int  CIW = CI / 32;
    constexpr int  WST = (CIW % 8 == 0) ? CIW + 4 : CIW;   // bank-conflict pad
    constexpr bool POOL = Cfg<L>::POOL, OUTF = Cfg<L>::OUTF;

    __shared__ __align__(16) unsigned int xs[H * W * CIW];
    __shared__ __align__(16) unsigned int ws[9 * 32 * WST];  // [tap][lane][wi]

    int n = blockIdx.x, cg = blockIdx.y;
    int tid = threadIdx.x;

    const unsigned int* xin = bc_in<L>() + n * H * W * CIW;
    const unsigned int* wbg = wb_ptr<L>();
    for (int i = tid; i < H * W * CIW; i += 256) xs[i] = xin[i];
    for (int i = tid; i < 9 * 32 * CIW; i += 256) {
        int tap = i / (32 * CIW);
        int rem = i % (32 * CIW);           // = lane*CIW + wi
        int ln = rem / CIW, wi = rem % CIW;
        ws[(tap * 32 + ln) * WST + wi] = wbg[(tap * CO + cg * 32) * CIW + rem];
    }
    __syncthreads();

    int lane = tid & 31, warp = tid >> 5;
    int co = cg * 32 + lane;
    float sc = scale[co], bi = bias[co];

    if constexpr (POOL) {
        constexpr int PH = H / 2, PW = W / 2;
        for (int pp = warp; pp < PH * PW; pp += 8) {
            int py = pp / PW, px = pp % PW;
            int pops[4] = {0, 0, 0, 0};
            int taps[4] = {0, 0, 0, 0};
            #pragma unroll
            for (int ky = -1; ky <= 1; ky++)
                #pragma unroll
                for (int kx = -1; kx <= 1; kx++) {
                    // weights for this tap, reused across the 4 pooled sub-pixels
                    const uint4* wv = reinterpret_cast<const uint4*>(
                        &ws[(((ky + 1) * 3 + kx + 1) * 32 + lane) * WST]);
                    uint4 wr[CIW / 4];
                    #pragma unroll
                    for (int v = 0; v < CIW / 4; v++) wr[v] = wv[v];
                    #pragma unroll
                    for (int s = 0; s < 4; s++) {
                        int y  = 2 * py + (s >> 1) + ky;
                        int xx = 2 * px + (s & 1) + kx;
                        if (y < 0 || y >= H || xx < 0 || xx >= W) continue;
                        taps[s]++;
                        const uint4* xp = reinterpret_cast<const uint4*>(&xs[(y * W + xx) * CIW]);
                        int p = 0;
                        #pragma unroll
                        for (int v = 0; v < CIW / 4; v++) {
                            uint4 a = xp[v];
                            p += __popc(a.x ^ wr[v].x) + __popc(a.y ^ wr[v].y)
                               + __popc(a.z ^ wr[v].z) + __popc(a.w ^ wr[v].w);
                        }
                        pops[s] += p;
                    }
                }
            int m = 0;  // relu(dot) then max-pool == max(0, max dots)
            #pragma unroll
            for (int s = 0; s < 4; s++) m = max(m, taps[s] * CI - 2 * pops[s]);
            float f = __fadd_rn(__fmul_rn((float)m, sc), bi);
            if constexpr (OUTF) {
                g_h6[((n * PH + py) * PW + px) * CO + co] = f;
            } else {
                unsigned int bits = __ballot_sync(0xffffffffu, f > 0.f);
                if (lane == 0)
                    bc_out<L>()[((n * PH + py) * PW + px) * (CO / 32) + cg] = bits;
            }
        }
    } else {
        for (int pp = warp; pp < H * W; pp += 8) {
            int y0 = pp / W, x0 = pp % W;
            int pop = 0, tapc = 0;
            #pragma unroll
            for (int ky = -1; ky <= 1; ky++)
                #pragma unroll
                for (int kx = -1; kx <= 1; kx++) {
                    int y = y0 + ky, xx = x0 + kx;
                    if (y < 0 || y >= H || xx < 0 || xx >= W) continue;
                    tapc++;
                    const uint4* wv = reinterpret_cast<const uint4*>(
                        &ws[(((ky + 1) * 3 + kx + 1) * 32 + lane) * WST]);
                    const uint4* xp = reinterpret_cast<const uint4*>(&xs[(y * W + xx) * CIW]);
                    #pragma unroll
                    for (int v = 0; v < CIW / 4; v++) {
                        uint4 a = xp[v], b = wv[v];
                        pop += __popc(a.x ^ b.x) + __popc(a.y ^ b.y)
                             + __popc(a.z ^ b.z) + __popc(a.w ^ b.w);
                    }
                }
            int dot = tapc * CI - 2 * pop;
            float f = __fadd_rn(__fmul_rn((float)max(dot, 0), sc), bi);  // relu then bn
            unsigned int bits = __ballot_sync(0xffffffffu, f > 0.f);
            if (lane == 0)
                bc_out<L>()[((n * H + y0) * W + x0) * (CO / 32) + cg] = bits;
        }
    }
}

// ---------------- fp32 dense(512->10) + softmax over last axis --------------
// one warp per (n, py, px): 128*16 = 2048 warps
__global__ void __launch_bounds__(256) dense_softmax_kernel(
    const float* __restrict__ dw, const float* __restrict__ db,
    float* __restrict__ out) {
    int gw = (blockIdx.x * blockDim.x + threadIdx.x) >> 5;
    int lane = threadIdx.x & 31;
    if (gw >= 2048) return;
    const float* hp = g_h6 + gw * 512;
    float acc[10];
    #pragma unroll
    for (int d = 0; d < 10; d++) acc[d] = 0.f;
    #pragma unroll 4
    for (int c = lane; c < 512; c += 32) {
        float hv = hp[c];
        #pragma unroll
        for (int d = 0; d < 10; d++)
            acc[d] = __fmaf_rn(hv, dw[c * 10 + d], acc[d]);
    }
    #pragma unroll
    for (int d = 0; d < 10; d++) {
        #pragma unroll
        for (int off = 16; off; off >>= 1)
            acc[d] += __shfl_xor_sync(0xffffffffu, acc[d], off);
    }
    if (lane == 0) {
        float mx = -1e30f;
        #pragma unroll
        for (int d = 0; d < 10; d++) {
            acc[d] = __fadd_rn(acc[d], db[d]);
            mx = fmaxf(mx, acc[d]);
        }
        float sum = 0.f;
        #pragma unroll
        for (int d = 0; d < 10; d++) {
            acc[d] = expf(__fadd_rn(acc[d], -mx));
            sum = __fadd_rn(sum, acc[d]);
        }
        #pragma unroll
        for (int d = 0; d < 10; d++) out[gw * 10 + d] = __fdiv_rn(acc[d], sum);
    }
}

// ---------------- launch ------------------------------------------------------
extern "C" void kernel_launch(void* const* d_in, const int* in_sizes, int n_in,
                              void* d_out, int out_size) {
    (void)n_in; (void)out_size;
    const float* x  = (const float*)d_in[0];
    const float* w1 = (const float*)d_in[1];
    const float* b1 = (const float*)d_in[2];

    // Resolve input ordering: dict order (w2 at idx 3, size 147456) vs
    // reference-signature order (bn1_scale at idx 3, size 128).
    int iw[7], ibs[7], ibb[7];
    if (in_sizes[3] == 147456) {           // dict order
        iw[2] = 3; iw[3] = 4; iw[4] = 5; iw[5] = 6; iw[6] = 7;
        for (int k = 1; k <= 6; k++) { ibs[k] = 8 + 2 * (k - 1); ibb[k] = 9 + 2 * (k - 1); }
    } else {                               // signature order
        ibs[1] = 3; ibb[1] = 4;
        for (int k = 2; k <= 6; k++) {
            iw[k]  = 5 + 3 * (k - 2);
            ibs[k] = 6 + 3 * (k - 2);
            ibb[k] = 7 + 3 * (k - 2);
        }
    }
    const float* dw = (const float*)d_in[20];
    const float* db = (const float*)d_in[21];
    float* out = (float*)d_out;

    // pack binary weights
    {
        int n2 = 9 * 128 * 4, n3 = 9 * 256 * 4, n4 = 9 * 256 * 8;
        int n5 = 9 * 512 * 8, n6 = 9 * 512 * 16;
        pack_kernel<2><<<(n2 + 255) / 256, 256>>>((const float*)d_in[iw[2]]);
        pack_kernel<3><<<(n3 + 255) / 256, 256>>>((const float*)d_in[iw[3]]);
        pack_kernel<4><<<(n4 + 255) / 256, 256>>>((const float*)d_in[iw[4]]);
        pack_kernel<5><<<(n5 + 255) / 256, 256>>>((const float*)d_in[iw[5]]);
        pack_kernel<6><<<(n6 + 255) / 256, 256>>>((const float*)d_in[iw[6]]);
    }

    conv1_kernel<<<dim3(32, 128), 128>>>(x, w1, b1,
        (const float*)d_in[ibs[1]], (const float*)d_in[ibb[1]]);

    binconv_kernel<2><<<dim3(128, 4),  256>>>((const float*)d_in[ibs[2]], (const float*)d_in[ibb[2]]);
    binconv_kernel<3><<<dim3(128, 8),  256>>>((const float*)d_in[ibs[3]], (const float*)d_in[ibb[3]]);
    binconv_kernel<4><<<dim3(128, 8),  256>>>((const float*)d_in[ibs[4]], (const float*)d_in[ibb[4]]);
    binconv_kernel<5><<<dim3(128, 16), 256>>>((const float*)d_in[ibs[5]], (const float*)d_in[ibb[5]]);
    binconv_kernel<6><<<dim3(128, 16), 256>>>((const float*)d_in[ibs[6]], (const float*)d_in[ibb[6]]);

    dense_softmax_kernel<<<256, 256>>>(dw, db, out);
}